// round 1
// baseline (speedup 1.0000x reference)
#include <cuda_runtime.h>
#include <cuda_bf16.h>
#include <math.h>

#define NS 16
#define NV 8
#define HE 32
#define DD 40
#define WN 640
#define NE 160000
#define NN 10000
#define C110 0.57735026918962576451f
#define C111 0.70710678118654752440f
#define EPSV 1e-5f

// ---------------- scratch (device globals; no allocations allowed) ----------------
__device__ __align__(16) float g_q[NN * DD];
__device__ __align__(16) float g_W1T[2][32 * 32];   // [branch][t*32+c]
__device__ __align__(16) float g_W2T[2][WN * 32];   // [branch][j*32+t]
__device__ __align__(16) float g_b1[2][32];
__device__ __align__(16) float g_b2[2][WN];
__device__ __align__(16) float g_attn[NE];
__device__ __align__(16) float g_vedge[(size_t)NE * DD];
__device__ unsigned g_mu[NN];
__device__ float g_mf[NN];
__device__ float g_denom[NN];
__device__ __align__(16) float g_num[NN * DD];      // reused as x buffer
__device__ float g_stats[48];                        // 16 sum, 16 sumsq, 8 vsq

// ---------------- helpers ----------------
__device__ __forceinline__ unsigned encf(float f) {
    unsigned u = __float_as_uint(f);
    return (u & 0x80000000u) ? ~u : (u | 0x80000000u);
}

__device__ __forceinline__ float dot32(const float (&rh)[32], const float* __restrict__ row, float bias) {
    const float4* wr = (const float4*)row;
    float s0 = bias, s1 = 0.f, s2 = 0.f, s3 = 0.f;
#pragma unroll
    for (int q = 0; q < 8; q++) {
        float4 w = wr[q];
        s0 = fmaf(rh[4 * q + 0], w.x, s0);
        s1 = fmaf(rh[4 * q + 1], w.y, s1);
        s2 = fmaf(rh[4 * q + 2], w.z, s2);
        s3 = fmaf(rh[4 * q + 3], w.w, s3);
    }
    return (s0 + s1) + (s2 + s3);
}

// ---------------- init ----------------
__global__ void init_kernel() {
    int i = blockIdx.x * blockDim.x + threadIdx.x;
    if (i < NN * DD) g_num[i] = 0.f;
    if (i < NN) { g_mu[i] = 0u; g_denom[i] = 0.f; }
    if (i < 48) g_stats[i] = 0.f;
}

// ---------------- weight transpose / copy ----------------
__global__ void prep_kernel(const float* __restrict__ kw1, const float* __restrict__ kb1,
                            const float* __restrict__ kw2, const float* __restrict__ kb2,
                            const float* __restrict__ vw1, const float* __restrict__ vb1,
                            const float* __restrict__ vw2, const float* __restrict__ vb2) {
    const int PER = WN * 32 + 1024 + 32 + WN;  // 22176
    int id = blockIdx.x * blockDim.x + threadIdx.x;
    if (id >= 2 * PER) return;
    int b = id / PER, r = id % PER;
    const float* w1 = b ? vw1 : kw1;
    const float* w2 = b ? vw2 : kw2;
    const float* b1 = b ? vb1 : kb1;
    const float* b2 = b ? vb2 : kb2;
    if (r < WN * 32) {
        int j = r >> 5, t = r & 31;
        g_W2T[b][r] = w2[t * WN + j];
    } else if (r < WN * 32 + 1024) {
        int q = r - WN * 32;
        int t = q >> 5, c = q & 31;
        g_W1T[b][q] = w1[c * 32 + t];
    } else if (r < WN * 32 + 1024 + 32) {
        int q = r - (WN * 32 + 1024);
        g_b1[b][q] = b1[q];
    } else {
        int q = r - (WN * 32 + 1024 + 32);
        g_b2[b][q] = b2[q];
    }
}

// ---------------- q projection (per node) ----------------
__global__ void qnode_kernel(const float* __restrict__ atom,
                             const float* __restrict__ Wqs, const float* __restrict__ Wqv) {
    __shared__ float sWs[256];
    __shared__ float sWv[64];
    int tid = threadIdx.x;
    if (tid < 256) sWs[tid] = Wqs[tid];
    if (tid < 64) sWv[tid] = Wqv[tid];
    __syncthreads();
    int n = blockIdx.x * 256 + tid;
    if (n >= NN) return;
    float xr[DD];
    const float4* p = (const float4*)(atom + (size_t)n * DD);
#pragma unroll
    for (int q = 0; q < 10; q++) {
        float4 t = p[q];
        xr[4 * q + 0] = t.x; xr[4 * q + 1] = t.y; xr[4 * q + 2] = t.z; xr[4 * q + 3] = t.w;
    }
    float qs[16];
#pragma unroll
    for (int o = 0; o < 16; o++) qs[o] = 0.f;
#pragma unroll
    for (int i = 0; i < 16; i++) {
        float xi = xr[i];
#pragma unroll
        for (int o = 0; o < 16; o++) qs[o] = fmaf(xi, sWs[i * 16 + o], qs[o]);
    }
    float qv[24];
#pragma unroll
    for (int o = 0; o < 24; o++) qv[o] = 0.f;
#pragma unroll
    for (int i = 0; i < 8; i++) {
#pragma unroll
        for (int o = 0; o < 8; o++) {
            float w = sWv[i * 8 + o];
            qv[3 * o + 0] = fmaf(xr[16 + 3 * i + 0], w, qv[3 * o + 0]);
            qv[3 * o + 1] = fmaf(xr[16 + 3 * i + 1], w, qv[3 * o + 1]);
            qv[3 * o + 2] = fmaf(xr[16 + 3 * i + 2], w, qv[3 * o + 2]);
        }
    }
    float* qp = g_q + (size_t)n * DD;
#pragma unroll
    for (int c = 0; c < 16; c++) qp[c] = qs[c];
#pragma unroll
    for (int c = 0; c < 24; c++) qp[16 + c] = qv[c];
}

// ---------------- edge branch (templated over branch index) ----------------
template <int B>
__device__ __forceinline__ void run_branch(const float (&rh)[32], const float (&xs)[16], const float (&xv)[24],
                                           float shs, float sv0, float sv1, float sv2, int tid,
                                           float* sW2, float* sb2, float (&outs)[16], float (&outv)[24]) {
#pragma unroll
    for (int o = 0; o < 16; o++) outs[o] = 0.f;
#pragma unroll
    for (int o = 0; o < 24; o++) outv[o] = 0.f;

    // ---- chunk 0: w1 region, rows 0..255 ----
    __syncthreads();
    {
        const float4* sp = (const float4*)(g_W2T[B]);
        float4* dp = (float4*)sW2;
        for (int i = tid; i < 256 * 8; i += 128) dp[i] = sp[i];
        for (int i = tid; i < 256; i += 128) sb2[i] = g_b2[B][i];
    }
    __syncthreads();
#pragma unroll 1
    for (int i = 0; i < 16; i++) {
        float a = xs[i] * shs;
#pragma unroll
        for (int o = 0; o < 16; o++) {
            float w = dot32(rh, sW2 + (i * 16 + o) * 32, sb2[i * 16 + o]);
            outs[o] = fmaf(w, a, outs[o]);
        }
    }

    // ---- chunk 1: w2 (rows 0..127) + w3 (rows 128..255), global rows 256..511 ----
    __syncthreads();
    {
        const float4* sp = (const float4*)(g_W2T[B] + 256 * 32);
        float4* dp = (float4*)sW2;
        for (int i = tid; i < 256 * 8; i += 128) dp[i] = sp[i];
        for (int i = tid; i < 256; i += 128) sb2[i] = g_b2[B][256 + i];
    }
    __syncthreads();
#pragma unroll 1
    for (int i = 0; i < 8; i++) {
        float di = C110 * (xv[3 * i] * sv0 + xv[3 * i + 1] * sv1 + xv[3 * i + 2] * sv2);
#pragma unroll
        for (int o = 0; o < 16; o++) {
            float w = dot32(rh, sW2 + (i * 16 + o) * 32, sb2[i * 16 + o]);
            outs[o] = fmaf(w, di, outs[o]);
        }
    }
    {
        float t3[8];
#pragma unroll
        for (int o = 0; o < 8; o++) t3[o] = 0.f;
#pragma unroll 1
        for (int i = 0; i < 16; i++) {
            float xi = xs[i];
#pragma unroll
            for (int o = 0; o < 8; o++) {
                float w = dot32(rh, sW2 + (128 + i * 8 + o) * 32, sb2[128 + i * 8 + o]);
                t3[o] = fmaf(w, xi, t3[o]);
            }
        }
#pragma unroll
        for (int o = 0; o < 8; o++) {
            outv[3 * o + 0] = fmaf(t3[o], sv0, outv[3 * o + 0]);
            outv[3 * o + 1] = fmaf(t3[o], sv1, outv[3 * o + 1]);
            outv[3 * o + 2] = fmaf(t3[o], sv2, outv[3 * o + 2]);
        }
    }

    // ---- chunk 2: w4 (rows 0..63) + w5 (rows 64..127), global rows 512..639 ----
    __syncthreads();
    {
        const float4* sp = (const float4*)(g_W2T[B] + 512 * 32);
        float4* dp = (float4*)sW2;
        for (int i = tid; i < 128 * 8; i += 128) dp[i] = sp[i];
        for (int i = tid; i < 128; i += 128) sb2[i] = g_b2[B][512 + i];
    }
    __syncthreads();
#pragma unroll 1
    for (int i = 0; i < 8; i++) {
        float v0 = xv[3 * i + 0] * shs, v1 = xv[3 * i + 1] * shs, v2 = xv[3 * i + 2] * shs;
#pragma unroll
        for (int o = 0; o < 8; o++) {
            float w = dot32(rh, sW2 + (i * 8 + o) * 32, sb2[i * 8 + o]);
            outv[3 * o + 0] = fmaf(w, v0, outv[3 * o + 0]);
            outv[3 * o + 1] = fmaf(w, v1, outv[3 * o + 1]);
            outv[3 * o + 2] = fmaf(w, v2, outv[3 * o + 2]);
        }
    }
#pragma unroll 1
    for (int i = 0; i < 8; i++) {
        float a0 = xv[3 * i + 0], a1 = xv[3 * i + 1], a2 = xv[3 * i + 2];
        float c0 = C111 * (a1 * sv2 - a2 * sv1);
        float c1 = C111 * (a2 * sv0 - a0 * sv2);
        float c2 = C111 * (a0 * sv1 - a1 * sv0);
#pragma unroll
        for (int o = 0; o < 8; o++) {
            float w = dot32(rh, sW2 + (64 + i * 8 + o) * 32, sb2[64 + i * 8 + o]);
            outv[3 * o + 0] = fmaf(w, c0, outv[3 * o + 0]);
            outv[3 * o + 1] = fmaf(w, c1, outv[3 * o + 1]);
            outv[3 * o + 2] = fmaf(w, c2, outv[3 * o + 2]);
        }
    }
}

// ---------------- main edge kernel ----------------
__global__ void __launch_bounds__(128, 2) edge_kernel(const float* __restrict__ atom,
                                                      const float* __restrict__ efeat,
                                                      const float* __restrict__ esh,
                                                      const int* __restrict__ eidx) {
    __shared__ float sW1[2048];
    __shared__ float sb1[64];
    __shared__ float sW2[256 * 32];
    __shared__ float sb2[256];
    const int tid = threadIdx.x;
    const int e = blockIdx.x * 128 + tid;

    for (int i = tid; i < 2048; i += 128) sW1[i] = ((const float*)g_W1T)[i];
    if (tid < 64) sb1[tid] = ((const float*)g_b1)[tid];
    __syncthreads();

    // edge features
    float efr[32];
    {
        const float4* p = (const float4*)(efeat + (size_t)e * HE);
#pragma unroll
        for (int q = 0; q < 8; q++) {
            float4 t = p[q];
            efr[4 * q + 0] = t.x; efr[4 * q + 1] = t.y; efr[4 * q + 2] = t.z; efr[4 * q + 3] = t.w;
        }
    }
    // hidden layers for both branches
    float rhk[32], rhv[32];
#pragma unroll 4
    for (int t = 0; t < 32; t++) {
        float a0 = sb1[t], a1 = sb1[32 + t];
        const float4* r0 = (const float4*)&sW1[t * 32];
        const float4* r1 = (const float4*)&sW1[1024 + t * 32];
#pragma unroll
        for (int q = 0; q < 8; q++) {
            float4 w0 = r0[q], w1 = r1[q];
            a0 = fmaf(efr[4 * q + 0], w0.x, a0); a0 = fmaf(efr[4 * q + 1], w0.y, a0);
            a0 = fmaf(efr[4 * q + 2], w0.z, a0); a0 = fmaf(efr[4 * q + 3], w0.w, a0);
            a1 = fmaf(efr[4 * q + 0], w1.x, a1); a1 = fmaf(efr[4 * q + 1], w1.y, a1);
            a1 = fmaf(efr[4 * q + 2], w1.z, a1); a1 = fmaf(efr[4 * q + 3], w1.w, a1);
        }
        rhk[t] = fmaxf(a0, 0.f);
        rhv[t] = fmaxf(a1, 0.f);
    }

    // destination-node features + spherical harmonics
    const int dst = eidx[e];
    const int src = eidx[NE + e];
    float xs[16], xv[24];
    {
        const float4* p = (const float4*)(atom + (size_t)dst * DD);
#pragma unroll
        for (int q = 0; q < 4; q++) {
            float4 t = p[q];
            xs[4 * q + 0] = t.x; xs[4 * q + 1] = t.y; xs[4 * q + 2] = t.z; xs[4 * q + 3] = t.w;
        }
#pragma unroll
        for (int q = 0; q < 6; q++) {
            float4 t = p[4 + q];
            xv[4 * q + 0] = t.x; xv[4 * q + 1] = t.y; xv[4 * q + 2] = t.z; xv[4 * q + 3] = t.w;
        }
    }
    float4 sh4 = *(const float4*)(esh + (size_t)e * 4);
    const float shs = sh4.x, sv0 = sh4.y, sv1 = sh4.z, sv2 = sh4.w;

    float outs[16], outv[24];

    // ---- k branch + attention logit ----
    run_branch<0>(rhk, xs, xv, shs, sv0, sv1, sv2, tid, sW2, sb2, outs, outv);
    {
        const float* qp = g_q + (size_t)src * DD;
        float acc = 0.f;
#pragma unroll
        for (int c = 0; c < 16; c++) acc = fmaf(outs[c], qp[c], acc);
#pragma unroll
        for (int c = 0; c < 24; c++) acc = fmaf(outv[c], qp[16 + c], acc);
        g_attn[e] = acc;
        atomicMax(&g_mu[src], encf(acc));
    }

    // ---- v branch ----
    run_branch<1>(rhv, xs, xv, shs, sv0, sv1, sv2, tid, sW2, sb2, outs, outv);
    {
        float* vp = g_vedge + (size_t)e * DD;
        float4* vp4 = (float4*)vp;
        vp4[0] = make_float4(outs[0], outs[1], outs[2], outs[3]);
        vp4[1] = make_float4(outs[4], outs[5], outs[6], outs[7]);
        vp4[2] = make_float4(outs[8], outs[9], outs[10], outs[11]);
        vp4[3] = make_float4(outs[12], outs[13], outs[14], outs[15]);
#pragma unroll
        for (int q = 0; q < 6; q++)
            vp4[4 + q] = make_float4(outv[4 * q + 0], outv[4 * q + 1], outv[4 * q + 2], outv[4 * q + 3]);
    }
}

// ---------------- decode segment max ----------------
__global__ void decode_kernel() {
    int n = blockIdx.x * 256 + threadIdx.x;
    if (n >= NN) return;
    unsigned u = g_mu[n];
    float f = (u & 0x80000000u) ? __uint_as_float(u ^ 0x80000000u) : __uint_as_float(~u);
    if (!isfinite(f)) f = 0.f;
    g_mf[n] = f;
}

// ---------------- exp + weighted accumulation ----------------
__global__ void expacc_kernel(const int* __restrict__ eidx) {
    int e = blockIdx.x * 256 + threadIdx.x;
    int src = eidx[NE + e];
    float ev = expf(g_attn[e] - g_mf[src]);
    atomicAdd(&g_denom[src], ev);
    const float4* vp = (const float4*)(g_vedge + (size_t)e * DD);
    float* np = g_num + (size_t)src * DD;
#pragma unroll
    for (int q = 0; q < 10; q++) {
        float4 v = vp[q];
        atomicAdd(&np[4 * q + 0], ev * v.x);
        atomicAdd(&np[4 * q + 1], ev * v.y);
        atomicAdd(&np[4 * q + 2], ev * v.z);
        atomicAdd(&np[4 * q + 3], ev * v.w);
    }
}

// ---------------- finalize A: residual + stats ----------------
__global__ void finalA_kernel(const float* __restrict__ atom) {
    __shared__ float sacc[48];
    int tid = threadIdx.x;
    int n = blockIdx.x * 256 + tid;
    if (tid < 48) sacc[tid] = 0.f;
    __syncthreads();
    if (n < NN) {
        float den = g_denom[n];
        float inv = (den != 0.f) ? 1.f / den : 0.f;
        float x[DD];
#pragma unroll
        for (int c = 0; c < DD; c++) {
            float v = atom[(size_t)n * DD + c] + g_num[(size_t)n * DD + c] * inv;
            x[c] = v;
            g_num[(size_t)n * DD + c] = v;
        }
#pragma unroll
        for (int c = 0; c < 16; c++) {
            atomicAdd(&sacc[c], x[c]);
            atomicAdd(&sacc[16 + c], x[c] * x[c]);
        }
#pragma unroll
        for (int i = 0; i < 8; i++) {
            float s = x[16 + 3 * i] * x[16 + 3 * i] + x[17 + 3 * i] * x[17 + 3 * i] + x[18 + 3 * i] * x[18 + 3 * i];
            atomicAdd(&sacc[32 + i], s);
        }
    }
    __syncthreads();
    if (tid < 48) atomicAdd(&g_stats[tid], sacc[tid]);
}

// ---------------- finalize B: batchnorm + write ----------------
__global__ void finalB_kernel(float* __restrict__ out,
                              const float* __restrict__ ws, const float* __restrict__ bs,
                              const float* __restrict__ wv) {
    int n = blockIdx.x * 256 + threadIdx.x;
    if (n >= NN) return;
    const float invN = 1.f / (float)NN;
#pragma unroll
    for (int c = 0; c < 16; c++) {
        float mu = g_stats[c] * invN;
        float var = g_stats[16 + c] * invN - mu * mu;
        float x = g_num[(size_t)n * DD + c];
        out[(size_t)n * DD + c] = (x - mu) / sqrtf(var + EPSV) * ws[c] + bs[c];
    }
#pragma unroll
    for (int i = 0; i < 8; i++) {
        float norm = g_stats[32 + i] * (invN * (1.f / 3.f));
        float sc = wv[i] / sqrtf(norm + EPSV);
#pragma unroll
        for (int d = 0; d < 3; d++) {
            float x = g_num[(size_t)n * DD + 16 + 3 * i + d];
            out[(size_t)n * DD + 16 + 3 * i + d] = x * sc;
        }
    }
}

// ---------------- launch ----------------
extern "C" void kernel_launch(void* const* d_in, const int* in_sizes, int n_in,
                              void* d_out, int out_size) {
    const float* atom  = (const float*)d_in[0];
    const float* efeat = (const float*)d_in[1];
    const float* esh   = (const float*)d_in[2];
    const float* Wqs   = (const float*)d_in[3];
    const float* Wqv   = (const float*)d_in[4];
    const float* kw1   = (const float*)d_in[5];
    const float* kb1   = (const float*)d_in[6];
    const float* kw2   = (const float*)d_in[7];
    const float* kb2   = (const float*)d_in[8];
    const float* vw1   = (const float*)d_in[9];
    const float* vb1   = (const float*)d_in[10];
    const float* vw2   = (const float*)d_in[11];
    const float* vb2   = (const float*)d_in[12];
    const float* bnws  = (const float*)d_in[13];
    const float* bnbs  = (const float*)d_in[14];
    const float* bnwv  = (const float*)d_in[15];
    const int*   eidx  = (const int*)d_in[16];
    float* out = (float*)d_out;

    init_kernel<<<(NN * DD + 255) / 256, 256>>>();
    prep_kernel<<<(2 * (WN * 32 + 1024 + 32 + WN) + 255) / 256, 256>>>(kw1, kb1, kw2, kb2, vw1, vb1, vw2, vb2);
    qnode_kernel<<<(NN + 255) / 256, 256>>>(atom, Wqs, Wqv);
    edge_kernel<<<NE / 128, 128>>>(atom, efeat, esh, eidx);
    decode_kernel<<<(NN + 255) / 256, 256>>>();
    expacc_kernel<<<NE / 256, 256>>>(eidx);
    finalA_kernel<<<(NN + 255) / 256, 256>>>(atom);
    finalB_kernel<<<(NN + 255) / 256, 256>>>(out, bnws, bnbs, bnwv);
    cudaMemcpyAsync(out + NN * DD, efeat, (size_t)NE * HE * sizeof(float),
                    cudaMemcpyDeviceToDevice);
}

// round 2
// speedup vs baseline: 1.3795x; 1.3795x over previous
#include <cuda_runtime.h>
#include <cuda_bf16.h>
#include <math.h>

#define NS 16
#define NV 8
#define HE 32
#define DD 40
#define WN 640
#define NE 160000
#define NN 10000
#define C110 0.57735026918962576451f
#define C111 0.70710678118654752440f
#define EPSV 1e-5f

typedef unsigned long long u64;

// ---------------- scratch (device globals; no allocations allowed) ----------------
__device__ __align__(16) float g_q[NN * DD];
__device__ __align__(16) float g_W1T[2][32 * 32];   // [branch][t*32+c]
__device__ __align__(16) float g_W2T[2][WN * 32];   // [branch][j*32+t]
__device__ __align__(16) float g_b1[2][32];
__device__ __align__(16) float g_b2[2][WN];
__device__ __align__(16) float g_attn[NE];
__device__ __align__(16) float g_vedge[(size_t)NE * DD];
__device__ __align__(16) float g_num[NN * DD];      // x buffer (pre-batchnorm)
__device__ float g_stats[48];                        // 16 sum, 16 sumsq, 8 vsq
__device__ int g_count[NN];
__device__ int g_off[NN + 1];
__device__ int g_cursor[NN];
__device__ int g_elist[NE];

// ---------------- packed f32x2 dot product (32-long) ----------------
__device__ __forceinline__ float dot32p(const u64 (&rh)[16], const float* __restrict__ row, float bias) {
    const ulonglong2* wp = (const ulonglong2*)row;
    u64 a0 = 0ULL, a1 = 0ULL, a2 = 0ULL, a3 = 0ULL;
#pragma unroll
    for (int q = 0; q < 4; q++) {
        ulonglong2 w0 = wp[2 * q];
        ulonglong2 w1 = wp[2 * q + 1];
        asm("fma.rn.f32x2 %0, %1, %2, %0;" : "+l"(a0) : "l"(rh[4 * q + 0]), "l"(w0.x));
        asm("fma.rn.f32x2 %0, %1, %2, %0;" : "+l"(a1) : "l"(rh[4 * q + 1]), "l"(w0.y));
        asm("fma.rn.f32x2 %0, %1, %2, %0;" : "+l"(a2) : "l"(rh[4 * q + 2]), "l"(w1.x));
        asm("fma.rn.f32x2 %0, %1, %2, %0;" : "+l"(a3) : "l"(rh[4 * q + 3]), "l"(w1.y));
    }
    asm("add.rn.f32x2 %0, %0, %1;" : "+l"(a0) : "l"(a1));
    asm("add.rn.f32x2 %0, %0, %1;" : "+l"(a2) : "l"(a3));
    asm("add.rn.f32x2 %0, %0, %1;" : "+l"(a0) : "l"(a2));
    float lo, hi;
    asm("mov.b64 {%0, %1}, %2;" : "=f"(lo), "=f"(hi) : "l"(a0));
    return (lo + hi) + bias;
}

__device__ __forceinline__ u64 packf2(float lo, float hi) {
    u64 p;
    asm("mov.b64 %0, {%1, %2};" : "=l"(p) : "f"(lo), "f"(hi));
    return p;
}

// ---------------- init ----------------
__global__ void init_kernel() {
    int i = blockIdx.x * blockDim.x + threadIdx.x;
    if (i < NN) g_count[i] = 0;
    if (i < 48) g_stats[i] = 0.f;
}

// ---------------- weight transpose / copy ----------------
__global__ void prep_kernel(const float* __restrict__ kw1, const float* __restrict__ kb1,
                            const float* __restrict__ kw2, const float* __restrict__ kb2,
                            const float* __restrict__ vw1, const float* __restrict__ vb1,
                            const float* __restrict__ vw2, const float* __restrict__ vb2) {
    const int PER = WN * 32 + 1024 + 32 + WN;  // 22176
    int id = blockIdx.x * blockDim.x + threadIdx.x;
    if (id >= 2 * PER) return;
    int b = id / PER, r = id % PER;
    const float* w1 = b ? vw1 : kw1;
    const float* w2 = b ? vw2 : kw2;
    const float* b1 = b ? vb1 : kb1;
    const float* b2 = b ? vb2 : kb2;
    if (r < WN * 32) {
        int j = r >> 5, t = r & 31;
        g_W2T[b][r] = w2[t * WN + j];
    } else if (r < WN * 32 + 1024) {
        int q = r - WN * 32;
        int t = q >> 5, c = q & 31;
        g_W1T[b][q] = w1[c * 32 + t];
    } else if (r < WN * 32 + 1024 + 32) {
        int q = r - (WN * 32 + 1024);
        g_b1[b][q] = b1[q];
    } else {
        int q = r - (WN * 32 + 1024 + 32);
        g_b2[b][q] = b2[q];
    }
}

// ---------------- q projection (per node) ----------------
__global__ void qnode_kernel(const float* __restrict__ atom,
                             const float* __restrict__ Wqs, const float* __restrict__ Wqv) {
    __shared__ float sWs[256];
    __shared__ float sWv[64];
    int tid = threadIdx.x;
    if (tid < 256) sWs[tid] = Wqs[tid];
    if (tid < 64) sWv[tid] = Wqv[tid];
    __syncthreads();
    int n = blockIdx.x * 256 + tid;
    if (n >= NN) return;
    float xr[DD];
    const float4* p = (const float4*)(atom + (size_t)n * DD);
#pragma unroll
    for (int q = 0; q < 10; q++) {
        float4 t = p[q];
        xr[4 * q + 0] = t.x; xr[4 * q + 1] = t.y; xr[4 * q + 2] = t.z; xr[4 * q + 3] = t.w;
    }
    float qs[16];
#pragma unroll
    for (int o = 0; o < 16; o++) qs[o] = 0.f;
#pragma unroll
    for (int i = 0; i < 16; i++) {
        float xi = xr[i];
#pragma unroll
        for (int o = 0; o < 16; o++) qs[o] = fmaf(xi, sWs[i * 16 + o], qs[o]);
    }
    float qv[24];
#pragma unroll
    for (int o = 0; o < 24; o++) qv[o] = 0.f;
#pragma unroll
    for (int i = 0; i < 8; i++) {
#pragma unroll
        for (int o = 0; o < 8; o++) {
            float w = sWv[i * 8 + o];
            qv[3 * o + 0] = fmaf(xr[16 + 3 * i + 0], w, qv[3 * o + 0]);
            qv[3 * o + 1] = fmaf(xr[16 + 3 * i + 1], w, qv[3 * o + 1]);
            qv[3 * o + 2] = fmaf(xr[16 + 3 * i + 2], w, qv[3 * o + 2]);
        }
    }
    float* qp = g_q + (size_t)n * DD;
#pragma unroll
    for (int c = 0; c < 16; c++) qp[c] = qs[c];
#pragma unroll
    for (int c = 0; c < 24; c++) qp[16 + c] = qv[c];
}

// ---------------- chunk load helper (128 rows x 32 floats) ----------------
__device__ __forceinline__ void load_chunk(const float* __restrict__ gsrc, const float* __restrict__ gb,
                                           float* sW2, float* sb2, int tid) {
    __syncthreads();
    const float4* sp = (const float4*)gsrc;
    float4* dp = (float4*)sW2;
#pragma unroll
    for (int q = 0; q < 8; q++) dp[tid + 128 * q] = sp[tid + 128 * q];
    if (tid < 128) sb2[tid] = gb[tid];
    __syncthreads();
}

// ---------------- edge branch (B = branch index) ----------------
template <int B>
__device__ __forceinline__ void run_branch(const u64 (&rh)[16], const float (&xs)[16], const float (&xv)[24],
                                           float shs, float sv0, float sv1, float sv2, int tid,
                                           float* sW2, float* sb2, float (&outs)[16], float (&outv)[24]) {
#pragma unroll
    for (int o = 0; o < 16; o++) outs[o] = 0.f;
#pragma unroll
    for (int o = 0; o < 24; o++) outv[o] = 0.f;

    // chunk 0: w1, i = 0..7
    load_chunk(g_W2T[B], g_b2[B], sW2, sb2, tid);
#pragma unroll 1
    for (int i = 0; i < 8; i++) {
        float a = xs[i] * shs;
#pragma unroll
        for (int o = 0; o < 16; o++) {
            float w = dot32p(rh, sW2 + (i * 16 + o) * 32, sb2[i * 16 + o]);
            outs[o] = fmaf(w, a, outs[o]);
        }
    }
    // chunk 1: w1, i = 8..15
    load_chunk(g_W2T[B] + 128 * 32, g_b2[B] + 128, sW2, sb2, tid);
#pragma unroll 1
    for (int i = 0; i < 8; i++) {
        float a = xs[8 + i] * shs;
#pragma unroll
        for (int o = 0; o < 16; o++) {
            float w = dot32p(rh, sW2 + (i * 16 + o) * 32, sb2[i * 16 + o]);
            outs[o] = fmaf(w, a, outs[o]);
        }
    }
    // chunk 2: w2 (8x16), rows 256..383
    load_chunk(g_W2T[B] + 256 * 32, g_b2[B] + 256, sW2, sb2, tid);
#pragma unroll 1
    for (int i = 0; i < 8; i++) {
        float di = C110 * (xv[3 * i] * sv0 + xv[3 * i + 1] * sv1 + xv[3 * i + 2] * sv2);
#pragma unroll
        for (int o = 0; o < 16; o++) {
            float w = dot32p(rh, sW2 + (i * 16 + o) * 32, sb2[i * 16 + o]);
            outs[o] = fmaf(w, di, outs[o]);
        }
    }
    // chunk 3: w3 (16x8), rows 384..511
    load_chunk(g_W2T[B] + 384 * 32, g_b2[B] + 384, sW2, sb2, tid);
    {
        float t3[8];
#pragma unroll
        for (int o = 0; o < 8; o++) t3[o] = 0.f;
#pragma unroll 1
        for (int i = 0; i < 16; i++) {
            float xi = xs[i];
#pragma unroll
            for (int o = 0; o < 8; o++) {
                float w = dot32p(rh, sW2 + (i * 8 + o) * 32, sb2[i * 8 + o]);
                t3[o] = fmaf(w, xi, t3[o]);
            }
        }
#pragma unroll
        for (int o = 0; o < 8; o++) {
            outv[3 * o + 0] = fmaf(t3[o], sv0, outv[3 * o + 0]);
            outv[3 * o + 1] = fmaf(t3[o], sv1, outv[3 * o + 1]);
            outv[3 * o + 2] = fmaf(t3[o], sv2, outv[3 * o + 2]);
        }
    }
    // chunk 4: w4 (rows 0..63 local) + w5 (rows 64..127 local), global 512..639
    load_chunk(g_W2T[B] + 512 * 32, g_b2[B] + 512, sW2, sb2, tid);
#pragma unroll 1
    for (int i = 0; i < 8; i++) {
        float v0 = xv[3 * i + 0] * shs, v1 = xv[3 * i + 1] * shs, v2 = xv[3 * i + 2] * shs;
#pragma unroll
        for (int o = 0; o < 8; o++) {
            float w = dot32p(rh, sW2 + (i * 8 + o) * 32, sb2[i * 8 + o]);
            outv[3 * o + 0] = fmaf(w, v0, outv[3 * o + 0]);
            outv[3 * o + 1] = fmaf(w, v1, outv[3 * o + 1]);
            outv[3 * o + 2] = fmaf(w, v2, outv[3 * o + 2]);
        }
    }
#pragma unroll 1
    for (int i = 0; i < 8; i++) {
        float a0 = xv[3 * i + 0], a1 = xv[3 * i + 1], a2 = xv[3 * i + 2];
        float c0 = C111 * (a1 * sv2 - a2 * sv1);
        float c1 = C111 * (a2 * sv0 - a0 * sv2);
        float c2 = C111 * (a0 * sv1 - a1 * sv0);
#pragma unroll
        for (int o = 0; o < 8; o++) {
            float w = dot32p(rh, sW2 + (64 + i * 8 + o) * 32, sb2[64 + i * 8 + o]);
            outv[3 * o + 0] = fmaf(w, c0, outv[3 * o + 0]);
            outv[3 * o + 1] = fmaf(w, c1, outv[3 * o + 1]);
            outv[3 * o + 2] = fmaf(w, c2, outv[3 * o + 2]);
        }
    }
}

// ---------------- main edge kernel ----------------
__global__ void __launch_bounds__(128, 3) edge_kernel(const float* __restrict__ atom,
                                                      const float* __restrict__ efeat,
                                                      const float* __restrict__ esh,
                                                      const int* __restrict__ eidx) {
    __shared__ float sW1[2048];
    __shared__ float sb1[64];
    __shared__ float sW2[128 * 32];
    __shared__ float sb2[128];
    __shared__ u64 srhv[16 * 128];
    const int tid = threadIdx.x;
    const int e = blockIdx.x * 128 + tid;

    for (int i = tid; i < 2048; i += 128) sW1[i] = ((const float*)g_W1T)[i];
    if (tid < 64) sb1[tid] = ((const float*)g_b1)[tid];
    __syncthreads();

    // packed edge features
    u64 efp[16];
    {
        const ulonglong2* p = (const ulonglong2*)(efeat + (size_t)e * HE);
#pragma unroll
        for (int q = 0; q < 8; q++) {
            ulonglong2 t = p[q];
            efp[2 * q] = t.x; efp[2 * q + 1] = t.y;
        }
    }
    // hidden layers (both branches); k kept in regs, v stashed to smem
    u64 rhk[16];
#pragma unroll 2
    for (int t = 0; t < 32; t += 2) {
        float k0 = fmaxf(dot32p(efp, sW1 + t * 32, sb1[t]), 0.f);
        float k1 = fmaxf(dot32p(efp, sW1 + (t + 1) * 32, sb1[t + 1]), 0.f);
        rhk[t >> 1] = packf2(k0, k1);
        float v0 = fmaxf(dot32p(efp, sW1 + 1024 + t * 32, sb1[32 + t]), 0.f);
        float v1 = fmaxf(dot32p(efp, sW1 + 1024 + (t + 1) * 32, sb1[33 + t]), 0.f);
        srhv[(t >> 1) * 128 + tid] = packf2(v0, v1);
    }

    // destination-node features + spherical harmonics
    const int dst = eidx[e];
    const int src = eidx[NE + e];
    atomicAdd(&g_count[src], 1);
    float xs[16], xv[24];
    {
        const float4* p = (const float4*)(atom + (size_t)dst * DD);
#pragma unroll
        for (int q = 0; q < 4; q++) {
            float4 t = p[q];
            xs[4 * q + 0] = t.x; xs[4 * q + 1] = t.y; xs[4 * q + 2] = t.z; xs[4 * q + 3] = t.w;
        }
#pragma unroll
        for (int q = 0; q < 6; q++) {
            float4 t = p[4 + q];
            xv[4 * q + 0] = t.x; xv[4 * q + 1] = t.y; xv[4 * q + 2] = t.z; xv[4 * q + 3] = t.w;
        }
    }
    float4 sh4 = *(const float4*)(esh + (size_t)e * 4);
    const float shs = sh4.x, sv0 = sh4.y, sv1 = sh4.z, sv2 = sh4.w;

    float outs[16], outv[24];

    // ---- k branch + attention logit ----
    run_branch<0>(rhk, xs, xv, shs, sv0, sv1, sv2, tid, sW2, sb2, outs, outv);
    {
        const float* qp = g_q + (size_t)src * DD;
        float acc = 0.f;
#pragma unroll
        for (int c = 0; c < 16; c++) acc = fmaf(outs[c], qp[c], acc);
#pragma unroll
        for (int c = 0; c < 24; c++) acc = fmaf(outv[c], qp[16 + c], acc);
        g_attn[e] = acc;
    }

    // ---- v branch (reload stashed hidden) ----
    u64 rhv[16];
#pragma unroll
    for (int q = 0; q < 16; q++) rhv[q] = srhv[q * 128 + tid];
    run_branch<1>(rhv, xs, xv, shs, sv0, sv1, sv2, tid, sW2, sb2, outs, outv);
    {
        float4* vp4 = (float4*)(g_vedge + (size_t)e * DD);
        vp4[0] = make_float4(outs[0], outs[1], outs[2], outs[3]);
        vp4[1] = make_float4(outs[4], outs[5], outs[6], outs[7]);
        vp4[2] = make_float4(outs[8], outs[9], outs[10], outs[11]);
        vp4[3] = make_float4(outs[12], outs[13], outs[14], outs[15]);
#pragma unroll
        for (int q = 0; q < 6; q++)
            vp4[4 + q] = make_float4(outv[4 * q + 0], outv[4 * q + 1], outv[4 * q + 2], outv[4 * q + 3]);
    }
}

// ---------------- CSR build: scan ----------------
__global__ void scan_kernel() {
    __shared__ int part[256];
    int tid = threadIdx.x;
    const int CH = (NN + 255) / 256;  // 40
    int beg = tid * CH;
    int end = beg + CH < NN ? beg + CH : NN;
    int s = 0;
    for (int i = beg; i < end; i++) s += g_count[i];
    part[tid] = s;
    __syncthreads();
    if (tid == 0) {
        int acc = 0;
        for (int i = 0; i < 256; i++) { int t = part[i]; part[i] = acc; acc += t; }
    }
    __syncthreads();
    int acc = part[tid];
    for (int i = beg; i < end; i++) {
        g_off[i] = acc;
        g_cursor[i] = acc;
        acc += g_count[i];
    }
    if (tid == 255) g_off[NN] = acc;
}

// ---------------- CSR build: scatter ----------------
__global__ void scatter_kernel(const int* __restrict__ eidx) {
    int e = blockIdx.x * 256 + threadIdx.x;
    int src = eidx[NE + e];
    int pos = atomicAdd(&g_cursor[src], 1);
    g_elist[pos] = e;
}

// ---------------- per-node softmax + aggregation + residual + stats ----------------
__global__ void gather_kernel(const float* __restrict__ atom) {
    __shared__ float sacc[48];
    int tid = threadIdx.x;
    if (tid < 48) sacc[tid] = 0.f;
    __syncthreads();
    int lane = tid & 31;
    int n = blockIdx.x * 4 + (tid >> 5);
    float x0 = 0.f, x1 = 0.f;
    {
        int beg = g_off[n], end = g_off[n + 1];
        float m = -INFINITY;
        for (int j = beg + lane; j < end; j += 32) m = fmaxf(m, g_attn[g_elist[j]]);
#pragma unroll
        for (int o = 16; o; o >>= 1) m = fmaxf(m, __shfl_xor_sync(~0u, m, o));
        if (!isfinite(m)) m = 0.f;
        float ds = 0.f;
        for (int j = beg + lane; j < end; j += 32) ds += expf(g_attn[g_elist[j]] - m);
#pragma unroll
        for (int o = 16; o; o >>= 1) ds += __shfl_xor_sync(~0u, ds, o);
        float a0 = 0.f, a1 = 0.f;
        for (int j = beg; j < end; j++) {
            int e = g_elist[j];
            float ev = expf(g_attn[e] - m);
            const float* vp = g_vedge + (size_t)e * DD;
            a0 = fmaf(ev, vp[lane], a0);
            if (lane < 8) a1 = fmaf(ev, vp[32 + lane], a1);
        }
        float inv = (ds != 0.f) ? 1.f / ds : 0.f;
        x0 = atom[(size_t)n * DD + lane] + a0 * inv;
        g_num[(size_t)n * DD + lane] = x0;
        if (lane < 8) {
            x1 = atom[(size_t)n * DD + 32 + lane] + a1 * inv;
            g_num[(size_t)n * DD + 32 + lane] = x1;
        }
    }
    if (lane < 16) {
        atomicAdd(&sacc[lane], x0);
        atomicAdd(&sacc[16 + lane], x0 * x0);
    } else {
        atomicAdd(&sacc[32 + (lane - 16) / 3], x0 * x0);
    }
    if (lane < 8) atomicAdd(&sacc[32 + (lane + 16) / 3], x1 * x1);
    __syncthreads();
    if (tid < 48) atomicAdd(&g_stats[tid], sacc[tid]);
}

// ---------------- finalize: batchnorm + write ----------------
__global__ void finalB_kernel(float* __restrict__ out,
                              const float* __restrict__ ws, const float* __restrict__ bs,
                              const float* __restrict__ wv) {
    int n = blockIdx.x * 256 + threadIdx.x;
    if (n >= NN) return;
    const float invN = 1.f / (float)NN;
#pragma unroll
    for (int c = 0; c < 16; c++) {
        float mu = g_stats[c] * invN;
        float var = g_stats[16 + c] * invN - mu * mu;
        float x = g_num[(size_t)n * DD + c];
        out[(size_t)n * DD + c] = (x - mu) / sqrtf(var + EPSV) * ws[c] + bs[c];
    }
#pragma unroll
    for (int i = 0; i < 8; i++) {
        float norm = g_stats[32 + i] * (invN * (1.f / 3.f));
        float sc = wv[i] / sqrtf(norm + EPSV);
#pragma unroll
        for (int d = 0; d < 3; d++) {
            float x = g_num[(size_t)n * DD + 16 + 3 * i + d];
            out[(size_t)n * DD + 16 + 3 * i + d] = x * sc;
        }
    }
}

// ---------------- launch ----------------
extern "C" void kernel_launch(void* const* d_in, const int* in_sizes, int n_in,
                              void* d_out, int out_size) {
    const float* atom  = (const float*)d_in[0];
    const float* efeat = (const float*)d_in[1];
    const float* esh   = (const float*)d_in[2];
    const float* Wqs   = (const float*)d_in[3];
    const float* Wqv   = (const float*)d_in[4];
    const float* kw1   = (const float*)d_in[5];
    const float* kb1   = (const float*)d_in[6];
    const float* kw2   = (const float*)d_in[7];
    const float* kb2   = (const float*)d_in[8];
    const float* vw1   = (const float*)d_in[9];
    const float* vb1   = (const float*)d_in[10];
    const float* vw2   = (const float*)d_in[11];
    const float* vb2   = (const float*)d_in[12];
    const float* bnws  = (const float*)d_in[13];
    const float* bnbs  = (const float*)d_in[14];
    const float* bnwv  = (const float*)d_in[15];
    const int*   eidx  = (const int*)d_in[16];
    float* out = (float*)d_out;

    init_kernel<<<(NN + 255) / 256, 256>>>();
    prep_kernel<<<(2 * (WN * 32 + 1024 + 32 + WN) + 255) / 256, 256>>>(kw1, kb1, kw2, kb2, vw1, vb1, vw2, vb2);
    qnode_kernel<<<(NN + 255) / 256, 256>>>(atom, Wqs, Wqv);
    edge_kernel<<<NE / 128, 128>>>(atom, efeat, esh, eidx);
    scan_kernel<<<1, 256>>>();
    scatter_kernel<<<NE / 256, 256>>>(eidx);
    gather_kernel<<<NN / 4, 128>>>(atom);
    finalB_kernel<<<(NN + 255) / 256, 256>>>(out, bnws, bnbs, bnwv);
    cudaMemcpyAsync(out + NN * DD, efeat, (size_t)NE * HE * sizeof(float),
                    cudaMemcpyDeviceToDevice);
}

// round 3
// speedup vs baseline: 1.4819x; 1.0742x over previous
#include <cuda_runtime.h>
#include <cuda_bf16.h>
#include <math.h>

#define NS 16
#define NV 8
#define HE 32
#define DD 40
#define WN 640
#define NE 160000
#define NN 10000
#define C110 0.57735026918962576451f
#define C111 0.70710678118654752440f
#define EPSV 1e-5f

typedef unsigned long long u64;

// ---------------- scratch ----------------
__device__ __align__(16) float g_q[NN * DD];
__device__ __align__(16) float g_W1T[2][32 * 32];
__device__ __align__(16) float g_W2T[2][WN * 32];
__device__ __align__(16) float g_b1[2][32];
__device__ __align__(16) float g_b2[2][WN];
__device__ __align__(16) float g_attn[NE];
__device__ __align__(16) float g_vedge[(size_t)NE * DD];
__device__ __align__(16) float g_num[NN * DD];
__device__ float g_stats[48];
__device__ int g_count[NN];
__device__ int g_off[NN + 1];
__device__ int g_cursor[NN];
__device__ int g_elist[NE];

// ---------------- packed helpers ----------------
__device__ __forceinline__ u64 packf2(float lo, float hi) {
    u64 p;
    asm("mov.b64 %0, {%1, %2};" : "=l"(p) : "f"(lo), "f"(hi));
    return p;
}

// dual dot: one weight-row load feeds two packed dot products
__device__ __forceinline__ void dot2(const u64 (&ra)[16], const u64 (&rb)[16],
                                     const float* __restrict__ row, float bias,
                                     float& da, float& db) {
    const ulonglong2* wp = (const ulonglong2*)row;
    u64 a0 = 0ULL, a1 = 0ULL, a2 = 0ULL, a3 = 0ULL;
    u64 b0 = 0ULL, b1 = 0ULL, b2 = 0ULL, b3 = 0ULL;
#pragma unroll
    for (int q = 0; q < 4; q++) {
        ulonglong2 w0 = wp[2 * q];
        ulonglong2 w1 = wp[2 * q + 1];
        asm("fma.rn.f32x2 %0, %1, %2, %0;" : "+l"(a0) : "l"(ra[4 * q + 0]), "l"(w0.x));
        asm("fma.rn.f32x2 %0, %1, %2, %0;" : "+l"(b0) : "l"(rb[4 * q + 0]), "l"(w0.x));
        asm("fma.rn.f32x2 %0, %1, %2, %0;" : "+l"(a1) : "l"(ra[4 * q + 1]), "l"(w0.y));
        asm("fma.rn.f32x2 %0, %1, %2, %0;" : "+l"(b1) : "l"(rb[4 * q + 1]), "l"(w0.y));
        asm("fma.rn.f32x2 %0, %1, %2, %0;" : "+l"(a2) : "l"(ra[4 * q + 2]), "l"(w1.x));
        asm("fma.rn.f32x2 %0, %1, %2, %0;" : "+l"(b2) : "l"(rb[4 * q + 2]), "l"(w1.x));
        asm("fma.rn.f32x2 %0, %1, %2, %0;" : "+l"(a3) : "l"(ra[4 * q + 3]), "l"(w1.y));
        asm("fma.rn.f32x2 %0, %1, %2, %0;" : "+l"(b3) : "l"(rb[4 * q + 3]), "l"(w1.y));
    }
    asm("add.rn.f32x2 %0, %0, %1;" : "+l"(a0) : "l"(a1));
    asm("add.rn.f32x2 %0, %0, %1;" : "+l"(a2) : "l"(a3));
    asm("add.rn.f32x2 %0, %0, %1;" : "+l"(a0) : "l"(a2));
    asm("add.rn.f32x2 %0, %0, %1;" : "+l"(b0) : "l"(b1));
    asm("add.rn.f32x2 %0, %0, %1;" : "+l"(b2) : "l"(b3));
    asm("add.rn.f32x2 %0, %0, %1;" : "+l"(b0) : "l"(b2));
    float alo, ahi, blo, bhi;
    asm("mov.b64 {%0, %1}, %2;" : "=f"(alo), "=f"(ahi) : "l"(a0));
    asm("mov.b64 {%0, %1}, %2;" : "=f"(blo), "=f"(bhi) : "l"(b0));
    da = (alo + ahi) + bias;
    db = (blo + bhi) + bias;
}

// ---------------- init ----------------
__global__ void init_kernel() {
    int i = blockIdx.x * blockDim.x + threadIdx.x;
    if (i < NN) g_count[i] = 0;
    if (i < 48) g_stats[i] = 0.f;
}

// ---------------- weight transpose / copy ----------------
__global__ void prep_kernel(const float* __restrict__ kw1, const float* __restrict__ kb1,
                            const float* __restrict__ kw2, const float* __restrict__ kb2,
                            const float* __restrict__ vw1, const float* __restrict__ vb1,
                            const float* __restrict__ vw2, const float* __restrict__ vb2) {
    const int PER = WN * 32 + 1024 + 32 + WN;
    int id = blockIdx.x * blockDim.x + threadIdx.x;
    if (id >= 2 * PER) return;
    int b = id / PER, r = id % PER;
    const float* w1 = b ? vw1 : kw1;
    const float* w2 = b ? vw2 : kw2;
    const float* b1 = b ? vb1 : kb1;
    const float* b2 = b ? vb2 : kb2;
    if (r < WN * 32) {
        int j = r >> 5, t = r & 31;
        g_W2T[b][r] = w2[t * WN + j];
    } else if (r < WN * 32 + 1024) {
        int q = r - WN * 32;
        int t = q >> 5, c = q & 31;
        g_W1T[b][q] = w1[c * 32 + t];
    } else if (r < WN * 32 + 1024 + 32) {
        g_b1[b][r - (WN * 32 + 1024)] = b1[r - (WN * 32 + 1024)];
    } else {
        g_b2[b][r - (WN * 32 + 1024 + 32)] = b2[r - (WN * 32 + 1024 + 32)];
    }
}

// ---------------- q projection ----------------
__global__ void qnode_kernel(const float* __restrict__ atom,
                             const float* __restrict__ Wqs, const float* __restrict__ Wqv) {
    __shared__ float sWs[256];
    __shared__ float sWv[64];
    int tid = threadIdx.x;
    if (tid < 256) sWs[tid] = Wqs[tid];
    if (tid < 64) sWv[tid] = Wqv[tid];
    __syncthreads();
    int n = blockIdx.x * 256 + tid;
    if (n >= NN) return;
    float xr[DD];
    const float4* p = (const float4*)(atom + (size_t)n * DD);
#pragma unroll
    for (int q = 0; q < 10; q++) {
        float4 t = p[q];
        xr[4 * q + 0] = t.x; xr[4 * q + 1] = t.y; xr[4 * q + 2] = t.z; xr[4 * q + 3] = t.w;
    }
    float qs[16];
#pragma unroll
    for (int o = 0; o < 16; o++) qs[o] = 0.f;
#pragma unroll
    for (int i = 0; i < 16; i++) {
        float xi = xr[i];
#pragma unroll
        for (int o = 0; o < 16; o++) qs[o] = fmaf(xi, sWs[i * 16 + o], qs[o]);
    }
    float qv[24];
#pragma unroll
    for (int o = 0; o < 24; o++) qv[o] = 0.f;
#pragma unroll
    for (int i = 0; i < 8; i++) {
#pragma unroll
        for (int o = 0; o < 8; o++) {
            float w = sWv[i * 8 + o];
            qv[3 * o + 0] = fmaf(xr[16 + 3 * i + 0], w, qv[3 * o + 0]);
            qv[3 * o + 1] = fmaf(xr[16 + 3 * i + 1], w, qv[3 * o + 1]);
            qv[3 * o + 2] = fmaf(xr[16 + 3 * i + 2], w, qv[3 * o + 2]);
        }
    }
    float* qp = g_q + (size_t)n * DD;
#pragma unroll
    for (int c = 0; c < 16; c++) qp[c] = qs[c];
#pragma unroll
    for (int c = 0; c < 24; c++) qp[16 + c] = qv[c];
}

// ---------------- chunk load (128 rows x 32 floats) ----------------
__device__ __forceinline__ void load_chunk(const float* __restrict__ gsrc, const float* __restrict__ gb,
                                           float* sW2, float* sb2, int tid) {
    __syncthreads();
    const float4* sp = (const float4*)gsrc;
    float4* dp = (float4*)sW2;
#pragma unroll
    for (int q = 0; q < 8; q++) dp[tid + 128 * q] = sp[tid + 128 * q];
    if (tid < 128) sb2[tid] = gb[tid];
    __syncthreads();
}

// ---------------- edge branch: B=0 (k/attention), B=1 (v/store) ----------------
template <int B>
__device__ __forceinline__ void run_branch(const u64 (&rhA)[16], const u64 (&rhB)[16],
                                           const float (&xsA)[16], const float (&xsB)[16],
                                           const float (&xvA)[24], const float (&xvB)[24],
                                           float shsA, float sA0, float sA1, float sA2,
                                           float shsB, float sB0, float sB1, float sB2,
                                           int tid, int eA, int eB, int srcA, int srcB,
                                           float* sW2, float* sb2) {
    float outsA[16], outsB[16];
#pragma unroll
    for (int o = 0; o < 16; o++) { outsA[o] = 0.f; outsB[o] = 0.f; }

    // chunks 0,1: w1 (16x16)
    load_chunk(g_W2T[B], g_b2[B], sW2, sb2, tid);
#pragma unroll 1
    for (int i = 0; i < 8; i++) {
        float aA = xsA[i] * shsA, aB = xsB[i] * shsB;
#pragma unroll
        for (int o = 0; o < 16; o++) {
            float wA, wB;
            dot2(rhA, rhB, sW2 + (i * 16 + o) * 32, sb2[i * 16 + o], wA, wB);
            outsA[o] = fmaf(wA, aA, outsA[o]);
            outsB[o] = fmaf(wB, aB, outsB[o]);
        }
    }
    load_chunk(g_W2T[B] + 128 * 32, g_b2[B] + 128, sW2, sb2, tid);
#pragma unroll 1
    for (int i = 0; i < 8; i++) {
        float aA = xsA[8 + i] * shsA, aB = xsB[8 + i] * shsB;
#pragma unroll
        for (int o = 0; o < 16; o++) {
            float wA, wB;
            dot2(rhA, rhB, sW2 + (i * 16 + o) * 32, sb2[i * 16 + o], wA, wB);
            outsA[o] = fmaf(wA, aA, outsA[o]);
            outsB[o] = fmaf(wB, aB, outsB[o]);
        }
    }
    // chunk 2: w2 (8x16)
    load_chunk(g_W2T[B] + 256 * 32, g_b2[B] + 256, sW2, sb2, tid);
#pragma unroll 1
    for (int i = 0; i < 8; i++) {
        float dA = C110 * (xvA[3 * i] * sA0 + xvA[3 * i + 1] * sA1 + xvA[3 * i + 2] * sA2);
        float dB = C110 * (xvB[3 * i] * sB0 + xvB[3 * i + 1] * sB1 + xvB[3 * i + 2] * sB2);
#pragma unroll
        for (int o = 0; o < 16; o++) {
            float wA, wB;
            dot2(rhA, rhB, sW2 + (i * 16 + o) * 32, sb2[i * 16 + o], wA, wB);
            outsA[o] = fmaf(wA, dA, outsA[o]);
            outsB[o] = fmaf(wB, dB, outsB[o]);
        }
    }
    // ---- retire outs ----
    float accA = 0.f, accB = 0.f;
    if (B == 0) {
        const float4* qa = (const float4*)(g_q + (size_t)srcA * DD);
        const float4* qb = (const float4*)(g_q + (size_t)srcB * DD);
#pragma unroll
        for (int q = 0; q < 4; q++) {
            float4 ta = qa[q], tb = qb[q];
            accA = fmaf(outsA[4 * q + 0], ta.x, accA); accA = fmaf(outsA[4 * q + 1], ta.y, accA);
            accA = fmaf(outsA[4 * q + 2], ta.z, accA); accA = fmaf(outsA[4 * q + 3], ta.w, accA);
            accB = fmaf(outsB[4 * q + 0], tb.x, accB); accB = fmaf(outsB[4 * q + 1], tb.y, accB);
            accB = fmaf(outsB[4 * q + 2], tb.z, accB); accB = fmaf(outsB[4 * q + 3], tb.w, accB);
        }
    } else {
        float4* va = (float4*)(g_vedge + (size_t)eA * DD);
        float4* vb = (float4*)(g_vedge + (size_t)eB * DD);
#pragma unroll
        for (int q = 0; q < 4; q++) {
            va[q] = make_float4(outsA[4 * q + 0], outsA[4 * q + 1], outsA[4 * q + 2], outsA[4 * q + 3]);
            vb[q] = make_float4(outsB[4 * q + 0], outsB[4 * q + 1], outsB[4 * q + 2], outsB[4 * q + 3]);
        }
    }

    float outvA[24], outvB[24];
#pragma unroll
    for (int o = 0; o < 24; o++) { outvA[o] = 0.f; outvB[o] = 0.f; }

    // chunk 3: w3 (16x8)
    load_chunk(g_W2T[B] + 384 * 32, g_b2[B] + 384, sW2, sb2, tid);
#pragma unroll 1
    for (int i = 0; i < 16; i++) {
        float tA0 = xsA[i] * sA0, tA1 = xsA[i] * sA1, tA2 = xsA[i] * sA2;
        float tB0 = xsB[i] * sB0, tB1 = xsB[i] * sB1, tB2 = xsB[i] * sB2;
#pragma unroll
        for (int o = 0; o < 8; o++) {
            float wA, wB;
            dot2(rhA, rhB, sW2 + (i * 8 + o) * 32, sb2[i * 8 + o], wA, wB);
            outvA[3 * o + 0] = fmaf(wA, tA0, outvA[3 * o + 0]);
            outvA[3 * o + 1] = fmaf(wA, tA1, outvA[3 * o + 1]);
            outvA[3 * o + 2] = fmaf(wA, tA2, outvA[3 * o + 2]);
            outvB[3 * o + 0] = fmaf(wB, tB0, outvB[3 * o + 0]);
            outvB[3 * o + 1] = fmaf(wB, tB1, outvB[3 * o + 1]);
            outvB[3 * o + 2] = fmaf(wB, tB2, outvB[3 * o + 2]);
        }
    }
    // chunk 4: w4 + w5
    load_chunk(g_W2T[B] + 512 * 32, g_b2[B] + 512, sW2, sb2, tid);
#pragma unroll 1
    for (int i = 0; i < 8; i++) {
        float tA0 = xvA[3 * i + 0] * shsA, tA1 = xvA[3 * i + 1] * shsA, tA2 = xvA[3 * i + 2] * shsA;
        float tB0 = xvB[3 * i + 0] * shsB, tB1 = xvB[3 * i + 1] * shsB, tB2 = xvB[3 * i + 2] * shsB;
#pragma unroll
        for (int o = 0; o < 8; o++) {
            float wA, wB;
            dot2(rhA, rhB, sW2 + (i * 8 + o) * 32, sb2[i * 8 + o], wA, wB);
            outvA[3 * o + 0] = fmaf(wA, tA0, outvA[3 * o + 0]);
            outvA[3 * o + 1] = fmaf(wA, tA1, outvA[3 * o + 1]);
            outvA[3 * o + 2] = fmaf(wA, tA2, outvA[3 * o + 2]);
            outvB[3 * o + 0] = fmaf(wB, tB0, outvB[3 * o + 0]);
            outvB[3 * o + 1] = fmaf(wB, tB1, outvB[3 * o + 1]);
            outvB[3 * o + 2] = fmaf(wB, tB2, outvB[3 * o + 2]);
        }
    }
#pragma unroll 1
    for (int i = 0; i < 8; i++) {
        float aA0 = xvA[3 * i + 0], aA1 = xvA[3 * i + 1], aA2 = xvA[3 * i + 2];
        float cA0 = C111 * (aA1 * sA2 - aA2 * sA1);
        float cA1 = C111 * (aA2 * sA0 - aA0 * sA2);
        float cA2 = C111 * (aA0 * sA1 - aA1 * sA0);
        float aB0 = xvB[3 * i + 0], aB1 = xvB[3 * i + 1], aB2 = xvB[3 * i + 2];
        float cB0 = C111 * (aB1 * sB2 - aB2 * sB1);
        float cB1 = C111 * (aB2 * sB0 - aB0 * sB2);
        float cB2 = C111 * (aB0 * sB1 - aB1 * sB0);
#pragma unroll
        for (int o = 0; o < 8; o++) {
            float wA, wB;
            dot2(rhA, rhB, sW2 + (64 + i * 8 + o) * 32, sb2[64 + i * 8 + o], wA, wB);
            outvA[3 * o + 0] = fmaf(wA, cA0, outvA[3 * o + 0]);
            outvA[3 * o + 1] = fmaf(wA, cA1, outvA[3 * o + 1]);
            outvA[3 * o + 2] = fmaf(wA, cA2, outvA[3 * o + 2]);
            outvB[3 * o + 0] = fmaf(wB, cB0, outvB[3 * o + 0]);
            outvB[3 * o + 1] = fmaf(wB, cB1, outvB[3 * o + 1]);
            outvB[3 * o + 2] = fmaf(wB, cB2, outvB[3 * o + 2]);
        }
    }
    // ---- retire outv ----
    if (B == 0) {
        const float* qa = g_q + (size_t)srcA * DD + 16;
        const float* qb = g_q + (size_t)srcB * DD + 16;
#pragma unroll
        for (int c = 0; c < 24; c++) {
            accA = fmaf(outvA[c], qa[c], accA);
            accB = fmaf(outvB[c], qb[c], accB);
        }
        g_attn[eA] = accA;
        g_attn[eB] = accB;
    } else {
        float4* va = (float4*)(g_vedge + (size_t)eA * DD + 16);
        float4* vb = (float4*)(g_vedge + (size_t)eB * DD + 16);
#pragma unroll
        for (int q = 0; q < 6; q++) {
            va[q] = make_float4(outvA[4 * q + 0], outvA[4 * q + 1], outvA[4 * q + 2], outvA[4 * q + 3]);
            vb[q] = make_float4(outvB[4 * q + 0], outvB[4 * q + 1], outvB[4 * q + 2], outvB[4 * q + 3]);
        }
    }
}

// ---------------- main edge kernel: 2 edges per thread ----------------
__global__ void __launch_bounds__(128, 2) edge_kernel(const float* __restrict__ atom,
                                                      const float* __restrict__ efeat,
                                                      const float* __restrict__ esh,
                                                      const int* __restrict__ eidx) {
    __shared__ float sW1[2048];
    __shared__ float sb1[64];
    __shared__ float sW2[128 * 32];
    __shared__ float sb2[128];
    __shared__ u64 srhv[16 * 256];
    const int tid = threadIdx.x;
    const int eA = blockIdx.x * 256 + tid;
    const int eB = eA + 128;

    for (int i = tid; i < 2048; i += 128) sW1[i] = ((const float*)g_W1T)[i];
    if (tid < 64) sb1[tid] = ((const float*)g_b1)[tid];
    __syncthreads();

    u64 rhA[16], rhB[16];
    {
        u64 efA[16], efB[16];
        const ulonglong2* pa = (const ulonglong2*)(efeat + (size_t)eA * HE);
        const ulonglong2* pb = (const ulonglong2*)(efeat + (size_t)eB * HE);
#pragma unroll
        for (int q = 0; q < 8; q++) {
            ulonglong2 ta = pa[q], tb = pb[q];
            efA[2 * q] = ta.x; efA[2 * q + 1] = ta.y;
            efB[2 * q] = tb.x; efB[2 * q + 1] = tb.y;
        }
#pragma unroll 1
        for (int t = 0; t < 32; t += 2) {
            float kA0, kB0, kA1, kB1;
            dot2(efA, efB, sW1 + t * 32, sb1[t], kA0, kB0);
            dot2(efA, efB, sW1 + (t + 1) * 32, sb1[t + 1], kA1, kB1);
            rhA[t >> 1] = packf2(fmaxf(kA0, 0.f), fmaxf(kA1, 0.f));
            rhB[t >> 1] = packf2(fmaxf(kB0, 0.f), fmaxf(kB1, 0.f));
            float vA0, vB0, vA1, vB1;
            dot2(efA, efB, sW1 + 1024 + t * 32, sb1[32 + t], vA0, vB0);
            dot2(efA, efB, sW1 + 1024 + (t + 1) * 32, sb1[33 + t], vA1, vB1);
            srhv[(t >> 1) * 256 + tid] = packf2(fmaxf(vA0, 0.f), fmaxf(vA1, 0.f));
            srhv[(t >> 1) * 256 + 128 + tid] = packf2(fmaxf(vB0, 0.f), fmaxf(vB1, 0.f));
        }
    }

    const int dstA = eidx[eA], srcA = eidx[NE + eA];
    const int dstB = eidx[eB], srcB = eidx[NE + eB];
    atomicAdd(&g_count[srcA], 1);
    atomicAdd(&g_count[srcB], 1);

    float xsA[16], xvA[24], xsB[16], xvB[24];
    {
        const float4* pa = (const float4*)(atom + (size_t)dstA * DD);
        const float4* pb = (const float4*)(atom + (size_t)dstB * DD);
#pragma unroll
        for (int q = 0; q < 4; q++) {
            float4 t = pa[q];
            xsA[4 * q + 0] = t.x; xsA[4 * q + 1] = t.y; xsA[4 * q + 2] = t.z; xsA[4 * q + 3] = t.w;
            t = pb[q];
            xsB[4 * q + 0] = t.x; xsB[4 * q + 1] = t.y; xsB[4 * q + 2] = t.z; xsB[4 * q + 3] = t.w;
        }
#pragma unroll
        for (int q = 0; q < 6; q++) {
            float4 t = pa[4 + q];
            xvA[4 * q + 0] = t.x; xvA[4 * q + 1] = t.y; xvA[4 * q + 2] = t.z; xvA[4 * q + 3] = t.w;
            t = pb[4 + q];
            xvB[4 * q + 0] = t.x; xvB[4 * q + 1] = t.y; xvB[4 * q + 2] = t.z; xvB[4 * q + 3] = t.w;
        }
    }
    float4 shA = *(const float4*)(esh + (size_t)eA * 4);
    float4 shB = *(const float4*)(esh + (size_t)eB * 4);

    // k branch -> attention logits
    run_branch<0>(rhA, rhB, xsA, xsB, xvA, xvB,
                  shA.x, shA.y, shA.z, shA.w, shB.x, shB.y, shB.z, shB.w,
                  tid, eA, eB, srcA, srcB, sW2, sb2);

    // v branch (reload stashed hidden)
#pragma unroll
    for (int q = 0; q < 16; q++) {
        rhA[q] = srhv[q * 256 + tid];
        rhB[q] = srhv[q * 256 + 128 + tid];
    }
    run_branch<1>(rhA, rhB, xsA, xsB, xvA, xvB,
                  shA.x, shA.y, shA.z, shA.w, shB.x, shB.y, shB.z, shB.w,
                  tid, eA, eB, srcA, srcB, sW2, sb2);
}

// ---------------- CSR build: scan ----------------
__global__ void scan_kernel() {
    __shared__ int part[256];
    int tid = threadIdx.x;
    const int CH = (NN + 255) / 256;
    int beg = tid * CH;
    int end = beg + CH < NN ? beg + CH : NN;
    int s = 0;
    for (int i = beg; i < end; i++) s += g_count[i];
    part[tid] = s;
    __syncthreads();
    if (tid == 0) {
        int acc = 0;
        for (int i = 0; i < 256; i++) { int t = part[i]; part[i] = acc; acc += t; }
    }
    __syncthreads();
    int acc = part[tid];
    for (int i = beg; i < end; i++) {
        g_off[i] = acc;
        g_cursor[i] = acc;
        acc += g_count[i];
    }
    if (tid == 255) g_off[NN] = acc;
}

// ---------------- CSR build: scatter ----------------
__global__ void scatter_kernel(const int* __restrict__ eidx) {
    int e = blockIdx.x * 256 + threadIdx.x;
    int src = eidx[NE + e];
    int pos = atomicAdd(&g_cursor[src], 1);
    g_elist[pos] = e;
}

// ---------------- per-node softmax + aggregation + residual + stats ----------------
__global__ void gather_kernel(const float* __restrict__ atom) {
    __shared__ float sacc[48];
    int tid = threadIdx.x;
    if (tid < 48) sacc[tid] = 0.f;
    __syncthreads();
    int lane = tid & 31;
    int n = blockIdx.x * 4 + (tid >> 5);
    float x0 = 0.f, x1 = 0.f;
    {
        int beg = g_off[n], end = g_off[n + 1];
        float m = -INFINITY;
        for (int j = beg + lane; j < end; j += 32) m = fmaxf(m, g_attn[g_elist[j]]);
#pragma unroll
        for (int o = 16; o; o >>= 1) m = fmaxf(m, __shfl_xor_sync(~0u, m, o));
        if (!isfinite(m)) m = 0.f;
        float ds = 0.f;
        for (int j = beg + lane; j < end; j += 32) ds += expf(g_attn[g_elist[j]] - m);
#pragma unroll
        for (int o = 16; o; o >>= 1) ds += __shfl_xor_sync(~0u, ds, o);
        float a0 = 0.f, a1 = 0.f;
        for (int j = beg; j < end; j++) {
            int e = g_elist[j];
            float ev = expf(g_attn[e] - m);
            const float* vp = g_vedge + (size_t)e * DD;
            a0 = fmaf(ev, vp[lane], a0);
            if (lane < 8) a1 = fmaf(ev, vp[32 + lane], a1);
        }
        float inv = (ds != 0.f) ? 1.f / ds : 0.f;
        x0 = atom[(size_t)n * DD + lane] + a0 * inv;
        g_num[(size_t)n * DD + lane] = x0;
        if (lane < 8) {
            x1 = atom[(size_t)n * DD + 32 + lane] + a1 * inv;
            g_num[(size_t)n * DD + 32 + lane] = x1;
        }
    }
    if (lane < 16) {
        atomicAdd(&sacc[lane], x0);
        atomicAdd(&sacc[16 + lane], x0 * x0);
    } else {
        atomicAdd(&sacc[32 + (lane - 16) / 3], x0 * x0);
    }
    if (lane < 8) atomicAdd(&sacc[32 + (lane + 16) / 3], x1 * x1);
    __syncthreads();
    if (tid < 48) atomicAdd(&g_stats[tid], sacc[tid]);
}

// ---------------- finalize: batchnorm + write ----------------
__global__ void finalB_kernel(float* __restrict__ out,
                              const float* __restrict__ ws, const float* __restrict__ bs,
                              const float* __restrict__ wv) {
    int n = blockIdx.x * 256 + threadIdx.x;
    if (n >= NN) return;
    const float invN = 1.f / (float)NN;
#pragma unroll
    for (int c = 0; c < 16; c++) {
        float mu = g_stats[c] * invN;
        float var = g_stats[16 + c] * invN - mu * mu;
        float x = g_num[(size_t)n * DD + c];
        out[(size_t)n * DD + c] = (x - mu) / sqrtf(var + EPSV) * ws[c] + bs[c];
    }
#pragma unroll
    for (int i = 0; i < 8; i++) {
        float norm = g_stats[32 + i] * (invN * (1.f / 3.f));
        float sc = wv[i] / sqrtf(norm + EPSV);
#pragma unroll
        for (int d = 0; d < 3; d++) {
            float x = g_num[(size_t)n * DD + 16 + 3 * i + d];
            out[(size_t)n * DD + 16 + 3 * i + d] = x * sc;
        }
    }
}

// ---------------- launch ----------------
extern "C" void kernel_launch(void* const* d_in, const int* in_sizes, int n_in,
                              void* d_out, int out_size) {
    const float* atom  = (const float*)d_in[0];
    const float* efeat = (const float*)d_in[1];
    const float* esh   = (const float*)d_in[2];
    const float* Wqs   = (const float*)d_in[3];
    const float* Wqv   = (const float*)d_in[4];
    const float* kw1   = (const float*)d_in[5];
    const float* kb1   = (const float*)d_in[6];
    const float* kw2   = (const float*)d_in[7];
    const float* kb2   = (const float*)d_in[8];
    const float* vw1   = (const float*)d_in[9];
    const float* vb1   = (const float*)d_in[10];
    const float* vw2   = (const float*)d_in[11];
    const float* vb2   = (const float*)d_in[12];
    const float* bnws  = (const float*)d_in[13];
    const float* bnbs  = (const float*)d_in[14];
    const float* bnwv  = (const float*)d_in[15];
    const int*   eidx  = (const int*)d_in[16];
    float* out = (float*)d_out;

    init_kernel<<<(NN + 255) / 256, 256>>>();
    prep_kernel<<<(2 * (WN * 32 + 1024 + 32 + WN) + 255) / 256, 256>>>(kw1, kb1, kw2, kb2, vw1, vb1, vw2, vb2);
    qnode_kernel<<<(NN + 255) / 256, 256>>>(atom, Wqs, Wqv);
    edge_kernel<<<NE / 256, 128>>>(atom, efeat, esh, eidx);
    scan_kernel<<<1, 256>>>();
    scatter_kernel<<<NE / 256, 256>>>(eidx);
    gather_kernel<<<NN / 4, 128>>>(atom);
    finalB_kernel<<<(NN + 255) / 256, 256>>>(out, bnws, bnbs, bnwv);
    cudaMemcpyAsync(out + NN * DD, efeat, (size_t)NE * HE * sizeof(float),
                    cudaMemcpyDeviceToDevice);
}